// round 1
// baseline (speedup 1.0000x reference)
#include <cuda_runtime.h>

#define H 256
#define W 256
#define D 256
#define N_BOXES 2048

// 64 MB scratch for the summed-area table (device global: allowed, no alloc).
__device__ float g_sat[(size_t)H * W * D];

// Pass A: prefix sum along W. One thread per (h, d). Consecutive threads have
// consecutive d -> every load/store is a fully coalesced 1024B warp access.
__global__ void __launch_bounds__(256) sat_row_prefix(const float* __restrict__ feat) {
    int tid = blockIdx.x * blockDim.x + threadIdx.x;   // tid = h*D + d
    int h = tid >> 8;
    int d = tid & 255;
    const float* src = feat + (size_t)h * W * D + d;
    float*       dst = g_sat + (size_t)h * W * D + d;
    float acc = 0.0f;
#pragma unroll 8
    for (int w = 0; w < W; ++w) {
        acc += src[(size_t)w * D];
        dst[(size_t)w * D] = acc;
    }
}

// Pass B: prefix sum along H, in place. One thread per (w, d).
__global__ void __launch_bounds__(256) sat_col_prefix() {
    int tid = blockIdx.x * blockDim.x + threadIdx.x;   // tid = w*D + d
    int w = tid >> 8;
    int d = tid & 255;
    float* p = g_sat + (size_t)w * D + d;
    float acc = 0.0f;
#pragma unroll 8
    for (int h = 0; h < H; ++h) {
        size_t idx = (size_t)h * W * D;
        acc += p[idx];
        p[idx] = acc;
    }
}

__device__ __forceinline__ float sat_at(int r, int c, int d) {
    return g_sat[((size_t)r * W + c) * D + d];
}

// Gather: one block per box, one thread per channel. 4 corner lookups.
__global__ void __launch_bounds__(256) roi_gather(const float* __restrict__ boxes,
                                                  float* __restrict__ out) {
    int n = blockIdx.x;
    int d = threadIdx.x;

    float x1 = boxes[n * 4 + 0];
    float y1 = boxes[n * 4 + 1];
    float x2 = boxes[n * 4 + 2];
    float y2 = boxes[n * 4 + 3];

    // _bounds(lo_f, hi_f, size):
    //   lo = max(0, floor(lo_f*size))
    //   hi = round(hi_f*size + 0.5)   [jnp.round = half-to-even = rintf]
    //   hi = min(size, max(lo+1, hi))
    // NO fma contraction: match jax's separate mul + add rounding.
    int clo = max(0, (int)floorf(__fmul_rn(x1, 256.0f)));
    int chi = (int)rintf(__fadd_rn(__fmul_rn(x2, 256.0f), 0.5f));
    chi = min(W, max(clo + 1, chi));

    int rlo = max(0, (int)floorf(__fmul_rn(y1, 256.0f)));
    int rhi = (int)rintf(__fadd_rn(__fmul_rn(y2, 256.0f), 0.5f));
    rhi = min(H, max(rlo + 1, rhi));

    float s = sat_at(rhi - 1, chi - 1, d);
    if (rlo > 0)            s -= sat_at(rlo - 1, chi - 1, d);
    if (clo > 0)            s -= sat_at(rhi - 1, clo - 1, d);
    if (rlo > 0 && clo > 0) s += sat_at(rlo - 1, clo - 1, d);

    float cnt = (float)((rhi - rlo) * (chi - clo));
    out[(size_t)n * D + d] = s / cnt;
}

extern "C" void kernel_launch(void* const* d_in, const int* in_sizes, int n_in,
                              void* d_out, int out_size) {
    const float* feat  = (const float*)d_in[0];   // (256,256,256) fp32
    const float* boxes = (const float*)d_in[1];   // (2048,4) fp32
    float* out = (float*)d_out;                   // (2048,256) fp32

    sat_row_prefix<<<(H * D) / 256, 256>>>(feat);
    sat_col_prefix<<<(W * D) / 256, 256>>>();
    roi_gather<<<N_BOXES, 256>>>(boxes, out);
}